// round 9
// baseline (speedup 1.0000x reference)
#include <cuda_runtime.h>
#include <cstdint>

#define HH 1024
#define WW 1024
#define NPIX (HH*WW)
#define C_IN 8
#define C_HID 32
#define NIT 64
#define TILE 16

typedef unsigned long long u64;

// Ping-pong state (64 MB) + masks (8 MB) + weight repack staging, static device scratch.
__device__ float g_x[2][C_IN][NPIX];
__device__ unsigned g_mask[NIT][NPIX/32];
__device__ float g_pack[2304 + 256 + 32 + 8];

// Packed weights in constant memory: [tap][o] w1, [hid][o] w2, b1, b2.
#define W1P 0
#define W2P 2304
#define B1P 2560
#define B2P 2592
__constant__ __align__(16) float c_pack[2304 + 256 + 32 + 8];

// ---------------- packed f32x2 helpers ----------------
__device__ __forceinline__ u64 fma2(u64 a, u64 b, u64 c) {
    u64 d;
    asm("fma.rn.f32x2 %0, %1, %2, %3;" : "=l"(d) : "l"(a), "l"(b), "l"(c));
    return d;
}
__device__ __forceinline__ u64 dup2(float x) {
    u64 r;
    asm("mov.b64 %0, {%1, %1};" : "=l"(r) : "f"(x));
    return r;
}
__device__ __forceinline__ void unpack2(u64 v, float& lo, float& hi) {
    asm("mov.b64 {%0, %1}, %2;" : "=f"(lo), "=f"(hi) : "l"(v));
}

// ---------------- threefry2x32 (exact JAX semantics) ----------------
__device__ __forceinline__ uint32_t rotl32(uint32_t x, int d) {
    return (x << d) | (x >> (32 - d));
}
__device__ __forceinline__ void tf_round(uint32_t& x0, uint32_t& x1, int r) {
    x0 += x1; x1 = rotl32(x1, r); x1 ^= x0;
}
__device__ __forceinline__ uint2 threefry(uint32_t k0, uint32_t k1, uint32_t x0, uint32_t x1) {
    uint32_t k2 = k0 ^ k1 ^ 0x1BD11BDAu;
    x0 += k0; x1 += k1;
    tf_round(x0,x1,13); tf_round(x0,x1,15); tf_round(x0,x1,26); tf_round(x0,x1,6);
    x0 += k1; x1 += k2 + 1u;
    tf_round(x0,x1,17); tf_round(x0,x1,29); tf_round(x0,x1,16); tf_round(x0,x1,24);
    x0 += k2; x1 += k0 + 2u;
    tf_round(x0,x1,13); tf_round(x0,x1,15); tf_round(x0,x1,26); tf_round(x0,x1,6);
    x0 += k0; x1 += k1 + 3u;
    tf_round(x0,x1,17); tf_round(x0,x1,29); tf_round(x0,x1,16); tf_round(x0,x1,24);
    x0 += k1; x1 += k2 + 4u;
    tf_round(x0,x1,13); tf_round(x0,x1,15); tf_round(x0,x1,26); tf_round(x0,x1,6);
    x0 += k2; x1 += k0 + 5u;
    return make_uint2(x0, x1);
}

// ---------------- weight repack: OIHW -> [tap][o] (then D2D-copied into c_pack) ----------------
__global__ void repack_kernel(const float* __restrict__ W1, const float* __restrict__ b1,
                              const float* __restrict__ W2, const float* __restrict__ b2) {
    int i = blockIdx.x * blockDim.x + threadIdx.x;   // 2600 items
    if (i < 2304) {
        int o = i / 72, t = i % 72;
        g_pack[W1P + t * 32 + o] = W1[i];
    } else if (i < 2304 + 256) {
        int j = i - 2304;                            // W2: [o][c] -> [c][o]
        int o = j / 32, c = j % 32;
        g_pack[W2P + c * 8 + o] = W2[j];
    } else if (i < 2304 + 256 + 32) {
        g_pack[B1P + (i - 2560)] = b1[i - 2560];
    } else if (i < 2304 + 256 + 32 + 8) {
        g_pack[B2P + (i - 2592)] = b2[i - 2592];
    }
}

// ---------------- mask precompute (jax_threefry_partitionable=True) ----------------
__global__ void genmask_kernel() {
    int gid = blockIdx.x * blockDim.x + threadIdx.x;   // NIT * 32768 threads; 32 pixels each
    int t  = gid >> 15;
    int wq = gid & 32767;
    uint2 kt = threefry(0u, 42u, 0u, (uint32_t)t);
    unsigned m = 0u;
    unsigned base = (unsigned)wq * 32u;
    #pragma unroll 4
    for (int k = 0; k < 32; k++) {
        uint2 rv = threefry(kt.x, kt.y, 0u, base + (unsigned)k);
        uint32_t bits = rv.x ^ rv.y;
        if ((bits >> 9) > 0x400000u) m |= (1u << k);
    }
    g_mask[t][wq] = m;
}

// ---------------- bilinear upsample 8x8 -> 1024x1024 ----------------
__global__ void upsample_kernel(const float* __restrict__ seed) {
    int i = blockIdx.x * blockDim.x + threadIdx.x;
    if (i >= C_IN * NPIX) return;
    int ch = i / NPIX;
    int p  = i % NPIX;
    int r = p / WW, c = p % WW;
    float sr = (r + 0.5f) * (8.0f / HH) - 0.5f;
    float sc = (c + 0.5f) * (8.0f / WW) - 0.5f;
    float fr0 = floorf(sr), fc0 = floorf(sc);
    float fr = sr - fr0,    fc = sc - fc0;
    int r0 = (int)fr0, c0 = (int)fc0;
    int r1 = min(r0 + 1, 7), c1 = min(c0 + 1, 7);
    r0 = max(r0, 0); c0 = max(c0, 0);
    const float* s = seed + ch * 64;
    float v00 = s[r0*8 + c0], v01 = s[r0*8 + c1];
    float v10 = s[r1*8 + c0], v11 = s[r1*8 + c1];
    float v0 = v00 * (1.0f - fc) + v01 * fc;
    float v1 = v10 * (1.0f - fc) + v11 * fc;
    g_x[0][ch][p] = v0 * (1.0f - fr) + v1 * fr;
}

// ---------------- one NCA step: weights split across constant port AND smem port ----------------
__global__ __launch_bounds__(256) void step_kernel(int src, int iter)
{
    __shared__ __align__(16) float w1s[72 * 32];     // smem copy of W1 pack (LDS port)
    __shared__ __align__(16) float w2s[32 * 8];      // smem copy of W2 pack
    __shared__ float tile[C_IN][TILE + 2][TILE + 3];

    int tid = threadIdx.x;

    // populate smem weight copies from constant (uniform, cheap, once per block)
    for (int i = tid; i < 2304; i += 256) w1s[i] = c_pack[W1P + i];
    if (tid < 256) w2s[tid] = c_pack[W2P + tid];

    int col0 = blockIdx.x * TILE;
    int row0 = blockIdx.y * TILE;

    // load 18x18 halo tile per channel (zero-pad outside)
    for (int i = tid; i < C_IN * 18 * 18; i += 256) {
        int ch = i / (18 * 18);
        int r  = (i / 18) % 18;
        int c  = i % 18;
        int gr = row0 + r - 1, gc = col0 + c - 1;
        float v = 0.0f;
        if ((unsigned)gr < HH && (unsigned)gc < WW)
            v = g_x[src][ch][gr * WW + gc];
        tile[ch][r][c] = v;
    }
    __syncthreads();

    int tx = tid % TILE, ty = tid / TILE;

    // ---- conv3x3: 16 packed accumulators = 32 hidden channels ----
    u64 acc[16];
    {
        const ulonglong2* bp = (const ulonglong2*)&c_pack[B1P];
        #pragma unroll
        for (int k = 0; k < 8; k++) { ulonglong2 v = bp[k]; acc[2*k] = v.x; acc[2*k+1] = v.y; }
    }

    #pragma unroll 1
    for (int ci = 0; ci < C_IN; ci++) {
        #pragma unroll
        for (int ky = 0; ky < 3; ky++) {
            const float* trow = &tile[ci][ty + ky][tx];
            #pragma unroll
            for (int kx = 0; kx < 3; kx++) {
                u64 xd = dup2(trow[kx]);
                int tap = ci * 9 + ky * 3 + kx;
                const ulonglong2* wpc = (const ulonglong2*)&c_pack[W1P + tap * 32];
                const ulonglong2* wps = (const ulonglong2*)&w1s[tap * 32];
                // quads 0..3 via constant port (LDC.128), quads 4..7 via smem port (LDS.128)
                #pragma unroll
                for (int j = 0; j < 4; j++) {
                    ulonglong2 w = wpc[j];
                    acc[2*j]   = fma2(xd, w.x, acc[2*j]);
                    acc[2*j+1] = fma2(xd, w.y, acc[2*j+1]);
                }
                #pragma unroll
                for (int j = 4; j < 8; j++) {
                    ulonglong2 w = wps[j];
                    acc[2*j]   = fma2(xd, w.x, acc[2*j]);
                    acc[2*j+1] = fma2(xd, w.y, acc[2*j+1]);
                }
            }
        }
    }

    // ---- gelu (exact erf) + conv1x1, all in registers ----
    u64 dxp[4];
    {
        const ulonglong2* bp = (const ulonglong2*)&c_pack[B2P];
        ulonglong2 v0 = bp[0], v1 = bp[1];
        dxp[0] = v0.x; dxp[1] = v0.y; dxp[2] = v1.x; dxp[3] = v1.y;
    }
    #pragma unroll
    for (int j = 0; j < 16; j++) {
        float h0, h1;
        unpack2(acc[j], h0, h1);
        float g0 = 0.5f * h0 * (1.0f + erff(h0 * 0.7071067811865476f));
        float g1 = 0.5f * h1 * (1.0f + erff(h1 * 0.7071067811865476f));
        u64 g0d = dup2(g0), g1d = dup2(g1);
        {
            // even hidden channel: constant port
            const ulonglong2* wp = (const ulonglong2*)&c_pack[W2P + (2*j) * 8];
            ulonglong2 wa = wp[0], wb = wp[1];
            dxp[0] = fma2(g0d, wa.x, dxp[0]);
            dxp[1] = fma2(g0d, wa.y, dxp[1]);
            dxp[2] = fma2(g0d, wb.x, dxp[2]);
            dxp[3] = fma2(g0d, wb.y, dxp[3]);
        }
        {
            // odd hidden channel: smem port
            const ulonglong2* wp = (const ulonglong2*)&w2s[(2*j+1) * 8];
            ulonglong2 wa = wp[0], wb = wp[1];
            dxp[0] = fma2(g1d, wa.x, dxp[0]);
            dxp[1] = fma2(g1d, wa.y, dxp[1]);
            dxp[2] = fma2(g1d, wb.x, dxp[2]);
            dxp[3] = fma2(g1d, wb.y, dxp[3]);
        }
    }

    // ---- masked update ----
    int row = row0 + ty, col = col0 + tx;
    int p = row * WW + col;
    unsigned bits = g_mask[iter][p >> 5];
    float m = ((bits >> (p & 31)) & 1u) ? 0.1f : 0.0f;   // fold 0.1 into the mask
    int dst = src ^ 1;
    #pragma unroll
    for (int k = 0; k < 4; k++) {
        float d0, d1;
        unpack2(dxp[k], d0, d1);
        g_x[dst][2*k][p]   = tile[2*k][ty + 1][tx + 1]   + d0 * m;
        g_x[dst][2*k+1][p] = tile[2*k+1][ty + 1][tx + 1] + d1 * m;
    }
}

// ---------------- projection ----------------
__global__ void project_kernel(const float* __restrict__ Wp, const float* __restrict__ bp,
                               float* __restrict__ out) {
    int p = blockIdx.x * blockDim.x + threadIdx.x;
    if (p >= NPIX) return;
    float s = bp[0];
    #pragma unroll
    for (int ch = 0; ch < C_IN; ch++) s += g_x[0][ch][p] * Wp[ch];
    out[p] = s;
}

extern "C" void kernel_launch(void* const* d_in, const int* in_sizes, int n_in,
                              void* d_out, int out_size) {
    const float* seed = (const float*)d_in[0];
    const float* W1   = (const float*)d_in[1];
    const float* b1   = (const float*)d_in[2];
    const float* W2   = (const float*)d_in[3];
    const float* b2   = (const float*)d_in[4];
    const float* Wp   = (const float*)d_in[5];
    const float* bp   = (const float*)d_in[6];
    float* out = (float*)d_out;

    repack_kernel<<<(2600 + 255) / 256, 256>>>(W1, b1, W2, b2);
    // D2D copy of the repacked weights into constant memory (graph-capturable memcpy node)
    {
        const void* src_dev;
        cudaGetSymbolAddress((void**)&src_dev, g_pack);
        cudaMemcpyToSymbolAsync(c_pack, src_dev, sizeof(float) * (2304 + 256 + 32 + 8),
                                0, cudaMemcpyDeviceToDevice, 0);
    }

    upsample_kernel<<<(C_IN * NPIX + 255) / 256, 256>>>(seed);
    genmask_kernel<<<(NIT * 32768) / 256, 256>>>();

    dim3 grid(WW / TILE, HH / TILE);
    for (int s = 0; s < NIT; s++)
        step_kernel<<<grid, 256>>>(s & 1, s);
    // after 64 steps the result is back in buffer 0
    project_kernel<<<(NPIX + 255) / 256, 256>>>(Wp, bp, out);
}

// round 11
// speedup vs baseline: 1.3151x; 1.3151x over previous
#include <cuda_runtime.h>
#include <cstdint>

#define HH 1024
#define WW 1024
#define NPIX (HH*WW)
#define C_IN 8
#define C_HID 32
#define NIT 64
#define TILE 16

typedef unsigned long long u64;

// Ping-pong state (64 MB) + masks (8 MB) + weight repack staging, static device scratch.
__device__ float g_x[2][C_IN][NPIX];
__device__ unsigned g_mask[NIT][NPIX/32];
__device__ float g_pack[2304 + 256 + 32 + 8];

// Packed weights in constant memory: [tap][o] w1, [hid][o] w2, b1, b2.
#define W1P 0
#define W2P 2304
#define B1P 2560
#define B2P 2592
__constant__ __align__(16) float c_pack[2304 + 256 + 32 + 8];

// ---------------- packed f32x2 helpers ----------------
__device__ __forceinline__ u64 fma2(u64 a, u64 b, u64 c) {
    u64 d;
    asm("fma.rn.f32x2 %0, %1, %2, %3;" : "=l"(d) : "l"(a), "l"(b), "l"(c));
    return d;
}
__device__ __forceinline__ u64 dup2(float x) {
    u64 r;
    asm("mov.b64 %0, {%1, %1};" : "=l"(r) : "f"(x));
    return r;
}
__device__ __forceinline__ u64 pack2(float lo, float hi) {
    u64 r;
    asm("mov.b64 %0, {%1, %2};" : "=l"(r) : "f"(lo), "f"(hi));
    return r;
}
__device__ __forceinline__ void unpack2(u64 v, float& lo, float& hi) {
    asm("mov.b64 {%0, %1}, %2;" : "=f"(lo), "=f"(hi) : "l"(v));
}

// ---------------- threefry2x32 (exact JAX semantics) ----------------
__device__ __forceinline__ uint32_t rotl32(uint32_t x, int d) {
    return (x << d) | (x >> (32 - d));
}
__device__ __forceinline__ void tf_round(uint32_t& x0, uint32_t& x1, int r) {
    x0 += x1; x1 = rotl32(x1, r); x1 ^= x0;
}
__device__ __forceinline__ uint2 threefry(uint32_t k0, uint32_t k1, uint32_t x0, uint32_t x1) {
    uint32_t k2 = k0 ^ k1 ^ 0x1BD11BDAu;
    x0 += k0; x1 += k1;
    tf_round(x0,x1,13); tf_round(x0,x1,15); tf_round(x0,x1,26); tf_round(x0,x1,6);
    x0 += k1; x1 += k2 + 1u;
    tf_round(x0,x1,17); tf_round(x0,x1,29); tf_round(x0,x1,16); tf_round(x0,x1,24);
    x0 += k2; x1 += k0 + 2u;
    tf_round(x0,x1,13); tf_round(x0,x1,15); tf_round(x0,x1,26); tf_round(x0,x1,6);
    x0 += k0; x1 += k1 + 3u;
    tf_round(x0,x1,17); tf_round(x0,x1,29); tf_round(x0,x1,16); tf_round(x0,x1,24);
    x0 += k1; x1 += k2 + 4u;
    tf_round(x0,x1,13); tf_round(x0,x1,15); tf_round(x0,x1,26); tf_round(x0,x1,6);
    x0 += k2; x1 += k0 + 5u;
    return make_uint2(x0, x1);
}

// ---------------- weight repack: OIHW -> [tap][o] (then D2D-copied into c_pack) ----------------
__global__ void repack_kernel(const float* __restrict__ W1, const float* __restrict__ b1,
                              const float* __restrict__ W2, const float* __restrict__ b2) {
    int i = blockIdx.x * blockDim.x + threadIdx.x;   // 2600 items
    if (i < 2304) {
        int o = i / 72, t = i % 72;
        g_pack[W1P + t * 32 + o] = W1[i];
    } else if (i < 2304 + 256) {
        int j = i - 2304;                            // W2: [o][c] -> [c][o]
        int o = j / 32, c = j % 32;
        g_pack[W2P + c * 8 + o] = W2[j];
    } else if (i < 2304 + 256 + 32) {
        g_pack[B1P + (i - 2560)] = b1[i - 2560];
    } else if (i < 2304 + 256 + 32 + 8) {
        g_pack[B2P + (i - 2592)] = b2[i - 2592];
    }
}

// ---------------- mask precompute (jax_threefry_partitionable=True) ----------------
__global__ void genmask_kernel() {
    int gid = blockIdx.x * blockDim.x + threadIdx.x;   // NIT * 32768 threads; 32 pixels each
    int t  = gid >> 15;
    int wq = gid & 32767;
    uint2 kt = threefry(0u, 42u, 0u, (uint32_t)t);
    unsigned m = 0u;
    unsigned base = (unsigned)wq * 32u;
    #pragma unroll 4
    for (int k = 0; k < 32; k++) {
        uint2 rv = threefry(kt.x, kt.y, 0u, base + (unsigned)k);
        uint32_t bits = rv.x ^ rv.y;
        if ((bits >> 9) > 0x400000u) m |= (1u << k);
    }
    g_mask[t][wq] = m;
}

// ---------------- bilinear upsample 8x8 -> 1024x1024 ----------------
__global__ void upsample_kernel(const float* __restrict__ seed) {
    int i = blockIdx.x * blockDim.x + threadIdx.x;
    if (i >= C_IN * NPIX) return;
    int ch = i / NPIX;
    int p  = i % NPIX;
    int r = p / WW, c = p % WW;
    float sr = (r + 0.5f) * (8.0f / HH) - 0.5f;
    float sc = (c + 0.5f) * (8.0f / WW) - 0.5f;
    float fr0 = floorf(sr), fc0 = floorf(sc);
    float fr = sr - fr0,    fc = sc - fc0;
    int r0 = (int)fr0, c0 = (int)fc0;
    int r1 = min(r0 + 1, 7), c1 = min(c0 + 1, 7);
    r0 = max(r0, 0); c0 = max(c0, 0);
    const float* s = seed + ch * 64;
    float v00 = s[r0*8 + c0], v01 = s[r0*8 + c1];
    float v10 = s[r1*8 + c0], v11 = s[r1*8 + c1];
    float v0 = v00 * (1.0f - fc) + v01 * fc;
    float v1 = v10 * (1.0f - fc) + v11 * fc;
    g_x[0][ch][p] = v0 * (1.0f - fr) + v1 * fr;
}

// ---------------- one NCA step: channel-split, 2 px/thread, weights via constant port ----------------
// Block = 256 threads over a 16x16 pixel tile.
// half = tid>>7 selects hidden channels [half*16, half*16+16).
// Within a half: tx = idx%16, q = idx/16 (0..7) -> pixels (2q, tx) and (2q+1, tx).
// After conv+gelu, h is exchanged via smem; each thread then runs the 1x1 epilogue for ONE pixel:
//   tid<128 -> pixel (2q, tx), tid>=128 -> pixel (2q+1, tx).
#define HSTRIDE 18   // u64 row pitch: 144 B, 16B-aligned for every pixel (LDS.128-safe)

__global__ __launch_bounds__(256) void step_kernel(int src, int iter)
{
    __shared__ float tile[C_IN][TILE + 2][TILE + 4];   // halo tile, padded rows
    __shared__ __align__(16) u64 hbuf[256 * HSTRIDE];  // gelu'd hidden: [pixel][16 u64 = 32 ch]

    int tid  = threadIdx.x;
    int half = tid >> 7;          // channel half
    int idx  = tid & 127;
    int tx   = idx % 16;
    int q    = idx / 16;          // 0..7
    int rl   = 2 * q;             // local row of pixel 0

    int col0 = blockIdx.x * TILE;
    int row0 = blockIdx.y * TILE;

    // load 18x18 halo tile per channel (zero-pad outside)
    for (int i = tid; i < C_IN * 18 * 18; i += 256) {
        int ch = i / (18 * 18);
        int r  = (i / 18) % 18;
        int c  = i % 18;
        int gr = row0 + r - 1, gc = col0 + c - 1;
        float v = 0.0f;
        if ((unsigned)gr < HH && (unsigned)gc < WW)
            v = g_x[src][ch][gr * WW + gc];
        tile[ch][r][c] = v;
    }
    __syncthreads();

    // ---- conv3x3: 16 channels (this half) x 2 pixels -> 16 u64 accumulators ----
    u64 accA[8], accB[8];   // pixel (rl, tx) and (rl+1, tx)
    {
        const ulonglong2* bp = (const ulonglong2*)&c_pack[B1P + half * 16];
        #pragma unroll
        for (int k = 0; k < 4; k++) {
            ulonglong2 v = bp[k];
            accA[2*k] = v.x; accA[2*k+1] = v.y;
            accB[2*k] = v.x; accB[2*k+1] = v.y;
        }
    }

    #pragma unroll 1
    for (int ci = 0; ci < C_IN; ci++) {
        // 4 rows x 3 cols of x feed both pixels' 3x3 windows
        float xr[4][3];
        #pragma unroll
        for (int r = 0; r < 4; r++) {
            #pragma unroll
            for (int c = 0; c < 3; c++)
                xr[r][c] = tile[ci][rl + r][tx + c];
        }
        #pragma unroll
        for (int ky = 0; ky < 3; ky++) {
            #pragma unroll
            for (int kx = 0; kx < 3; kx++) {
                u64 x0 = dup2(xr[ky][kx]);
                u64 x1 = dup2(xr[ky + 1][kx]);
                int tap = ci * 9 + ky * 3 + kx;
                const ulonglong2* wp = (const ulonglong2*)&c_pack[W1P + tap * 32 + half * 16];
                #pragma unroll
                for (int j = 0; j < 4; j++) {
                    ulonglong2 w = wp[j];            // LDC.128: 4 weights of this half
                    accA[2*j]   = fma2(x0, w.x, accA[2*j]);
                    accA[2*j+1] = fma2(x0, w.y, accA[2*j+1]);
                    accB[2*j]   = fma2(x1, w.x, accB[2*j]);
                    accB[2*j+1] = fma2(x1, w.y, accB[2*j+1]);
                }
            }
        }
    }

    // ---- gelu (exact erf) in registers, store to exchange buffer ----
    {
        int pl0 = rl * 16 + tx;          // local pixel index of pixel 0
        u64* row0p = &hbuf[pl0 * HSTRIDE + half * 8];
        u64* row1p = &hbuf[(pl0 + 16) * HSTRIDE + half * 8];
        #pragma unroll
        for (int j = 0; j < 8; j++) {
            float a0, a1, b0, b1;
            unpack2(accA[j], a0, a1);
            unpack2(accB[j], b0, b1);
            float ga0 = 0.5f * a0 * (1.0f + erff(a0 * 0.7071067811865476f));
            float ga1 = 0.5f * a1 * (1.0f + erff(a1 * 0.7071067811865476f));
            float gb0 = 0.5f * b0 * (1.0f + erff(b0 * 0.7071067811865476f));
            float gb1 = 0.5f * b1 * (1.0f + erff(b1 * 0.7071067811865476f));
            row0p[j] = pack2(ga0, ga1);
            row1p[j] = pack2(gb0, gb1);
        }
    }
    __syncthreads();

    // ---- 1x1 conv epilogue: each thread handles ONE pixel, all 32 channels ----
    int prow = rl + half;                // tid<128 -> row rl, tid>=128 -> row rl+1
    int pl = prow * 16 + tx;
    const ulonglong2* hrow = (const ulonglong2*)&hbuf[pl * HSTRIDE];

    u64 dxp[4];
    {
        const ulonglong2* bp = (const ulonglong2*)&c_pack[B2P];
        ulonglong2 v0 = bp[0], v1 = bp[1];
        dxp[0] = v0.x; dxp[1] = v0.y; dxp[2] = v1.x; dxp[3] = v1.y;
    }
    #pragma unroll
    for (int k = 0; k < 8; k++) {        // 8 x LDS.128 = 32 hidden values
        ulonglong2 hv = hrow[k];
        float g0, g1, g2, g3;
        unpack2(hv.x, g0, g1);
        unpack2(hv.y, g2, g3);
        int c0 = 4 * k;
        #pragma unroll
        for (int s = 0; s < 4; s++) {
            float gv = (s == 0) ? g0 : (s == 1) ? g1 : (s == 2) ? g2 : g3;
            u64 gd = dup2(gv);
            const ulonglong2* wp = (const ulonglong2*)&c_pack[W2P + (c0 + s) * 8];
            ulonglong2 wa = wp[0], wb = wp[1];
            dxp[0] = fma2(gd, wa.x, dxp[0]);
            dxp[1] = fma2(gd, wa.y, dxp[1]);
            dxp[2] = fma2(gd, wb.x, dxp[2]);
            dxp[3] = fma2(gd, wb.y, dxp[3]);
        }
    }

    // ---- masked update ----
    int row = row0 + prow, col = col0 + tx;
    int p = row * WW + col;
    unsigned bits = g_mask[iter][p >> 5];
    float m = ((bits >> (p & 31)) & 1u) ? 0.1f : 0.0f;   // fold 0.1 into the mask
    int dst = src ^ 1;
    #pragma unroll
    for (int k = 0; k < 4; k++) {
        float d0, d1;
        unpack2(dxp[k], d0, d1);
        g_x[dst][2*k][p]   = tile[2*k][prow + 1][tx + 1]   + d0 * m;
        g_x[dst][2*k+1][p] = tile[2*k+1][prow + 1][tx + 1] + d1 * m;
    }
}

// ---------------- projection ----------------
__global__ void project_kernel(const float* __restrict__ Wp, const float* __restrict__ bp,
                               float* __restrict__ out) {
    int p = blockIdx.x * blockDim.x + threadIdx.x;
    if (p >= NPIX) return;
    float s = bp[0];
    #pragma unroll
    for (int ch = 0; ch < C_IN; ch++) s += g_x[0][ch][p] * Wp[ch];
    out[p] = s;
}

extern "C" void kernel_launch(void* const* d_in, const int* in_sizes, int n_in,
                              void* d_out, int out_size) {
    const float* seed = (const float*)d_in[0];
    const float* W1   = (const float*)d_in[1];
    const float* b1   = (const float*)d_in[2];
    const float* W2   = (const float*)d_in[3];
    const float* b2   = (const float*)d_in[4];
    const float* Wp   = (const float*)d_in[5];
    const float* bp   = (const float*)d_in[6];
    float* out = (float*)d_out;

    repack_kernel<<<(2600 + 255) / 256, 256>>>(W1, b1, W2, b2);
    // D2D copy of the repacked weights into constant memory (graph-capturable memcpy node)
    {
        const void* src_dev;
        cudaGetSymbolAddress((void**)&src_dev, g_pack);
        cudaMemcpyToSymbolAsync(c_pack, src_dev, sizeof(float) * (2304 + 256 + 32 + 8),
                                0, cudaMemcpyDeviceToDevice, 0);
    }

    upsample_kernel<<<(C_IN * NPIX + 255) / 256, 256>>>(seed);
    genmask_kernel<<<(NIT * 32768) / 256, 256>>>();

    dim3 grid(WW / TILE, HH / TILE);
    for (int s = 0; s < NIT; s++)
        step_kernel<<<grid, 256>>>(s & 1, s);
    // after 64 steps the result is back in buffer 0
    project_kernel<<<(NPIX + 255) / 256, 256>>>(Wp, bp, out);
}

// round 13
// speedup vs baseline: 1.7587x; 1.3374x over previous
#include <cuda_runtime.h>
#include <cstdint>

#define HH 1024
#define WW 1024
#define NPIX (HH*WW)
#define C_IN 8
#define C_HID 32
#define NIT 64
#define TW 16
#define TH 32

typedef unsigned long long u64;

// Ping-pong state (64 MB) + masks (8 MB) + weight repack staging, static device scratch.
__device__ float g_x[2][C_IN][NPIX];
__device__ unsigned g_mask[NIT][NPIX/32];
__device__ float g_pack[2304 + 256 + 32 + 8];

// Packed weights in constant memory: [tap][o] w1, [hid][o] w2, b1, b2.
#define W1P 0
#define W2P 2304
#define B1P 2560
#define B2P 2592
__constant__ __align__(16) float c_pack[2304 + 256 + 32 + 8];

// ---------------- packed f32x2 helpers ----------------
__device__ __forceinline__ u64 fma2(u64 a, u64 b, u64 c) {
    u64 d;
    asm("fma.rn.f32x2 %0, %1, %2, %3;" : "=l"(d) : "l"(a), "l"(b), "l"(c));
    return d;
}
__device__ __forceinline__ u64 dup2(float x) {
    u64 r;
    asm("mov.b64 %0, {%1, %1};" : "=l"(r) : "f"(x));
    return r;
}
__device__ __forceinline__ void unpack2(u64 v, float& lo, float& hi) {
    asm("mov.b64 {%0, %1}, %2;" : "=f"(lo), "=f"(hi) : "l"(v));
}
__device__ __forceinline__ float gelu1(float h) {
    return 0.5f * h * (1.0f + erff(h * 0.7071067811865476f));
}

// ---------------- threefry2x32 (exact JAX semantics) ----------------
__device__ __forceinline__ uint32_t rotl32(uint32_t x, int d) {
    return (x << d) | (x >> (32 - d));
}
__device__ __forceinline__ void tf_round(uint32_t& x0, uint32_t& x1, int r) {
    x0 += x1; x1 = rotl32(x1, r); x1 ^= x0;
}
__device__ __forceinline__ uint2 threefry(uint32_t k0, uint32_t k1, uint32_t x0, uint32_t x1) {
    uint32_t k2 = k0 ^ k1 ^ 0x1BD11BDAu;
    x0 += k0; x1 += k1;
    tf_round(x0,x1,13); tf_round(x0,x1,15); tf_round(x0,x1,26); tf_round(x0,x1,6);
    x0 += k1; x1 += k2 + 1u;
    tf_round(x0,x1,17); tf_round(x0,x1,29); tf_round(x0,x1,16); tf_round(x0,x1,24);
    x0 += k2; x1 += k0 + 2u;
    tf_round(x0,x1,13); tf_round(x0,x1,15); tf_round(x0,x1,26); tf_round(x0,x1,6);
    x0 += k0; x1 += k1 + 3u;
    tf_round(x0,x1,17); tf_round(x0,x1,29); tf_round(x0,x1,16); tf_round(x0,x1,24);
    x0 += k1; x1 += k2 + 4u;
    tf_round(x0,x1,13); tf_round(x0,x1,15); tf_round(x0,x1,26); tf_round(x0,x1,6);
    x0 += k2; x1 += k0 + 5u;
    return make_uint2(x0, x1);
}

// ---------------- weight repack: OIHW -> [tap][o] (then D2D-copied into c_pack) ----------------
__global__ void repack_kernel(const float* __restrict__ W1, const float* __restrict__ b1,
                              const float* __restrict__ W2, const float* __restrict__ b2) {
    int i = blockIdx.x * blockDim.x + threadIdx.x;   // 2600 items
    if (i < 2304) {
        int o = i / 72, t = i % 72;
        g_pack[W1P + t * 32 + o] = W1[i];
    } else if (i < 2304 + 256) {
        int j = i - 2304;                            // W2: [o][c] -> [c][o]
        int o = j / 32, c = j % 32;
        g_pack[W2P + c * 8 + o] = W2[j];
    } else if (i < 2304 + 256 + 32) {
        g_pack[B1P + (i - 2560)] = b1[i - 2560];
    } else if (i < 2304 + 256 + 32 + 8) {
        g_pack[B2P + (i - 2592)] = b2[i - 2592];
    }
}

// ---------------- mask precompute (jax_threefry_partitionable=True) ----------------
__global__ void genmask_kernel() {
    int gid = blockIdx.x * blockDim.x + threadIdx.x;   // NIT * 32768 threads; 32 pixels each
    int t  = gid >> 15;
    int wq = gid & 32767;
    uint2 kt = threefry(0u, 42u, 0u, (uint32_t)t);
    unsigned m = 0u;
    unsigned base = (unsigned)wq * 32u;
    #pragma unroll 4
    for (int k = 0; k < 32; k++) {
        uint2 rv = threefry(kt.x, kt.y, 0u, base + (unsigned)k);
        uint32_t bits = rv.x ^ rv.y;
        if ((bits >> 9) > 0x400000u) m |= (1u << k);
    }
    g_mask[t][wq] = m;
}

// ---------------- bilinear upsample 8x8 -> 1024x1024 ----------------
__global__ void upsample_kernel(const float* __restrict__ seed) {
    int i = blockIdx.x * blockDim.x + threadIdx.x;
    if (i >= C_IN * NPIX) return;
    int ch = i / NPIX;
    int p  = i % NPIX;
    int r = p / WW, c = p % WW;
    float sr = (r + 0.5f) * (8.0f / HH) - 0.5f;
    float sc = (c + 0.5f) * (8.0f / WW) - 0.5f;
    float fr0 = floorf(sr), fc0 = floorf(sc);
    float fr = sr - fr0,    fc = sc - fc0;
    int r0 = (int)fr0, c0 = (int)fc0;
    int r1 = min(r0 + 1, 7), c1 = min(c0 + 1, 7);
    r0 = max(r0, 0); c0 = max(c0, 0);
    const float* s = seed + ch * 64;
    float v00 = s[r0*8 + c0], v01 = s[r0*8 + c1];
    float v10 = s[r1*8 + c0], v11 = s[r1*8 + c1];
    float v0 = v00 * (1.0f - fc) + v01 * fc;
    float v1 = v10 * (1.0f - fc) + v11 * fc;
    g_x[0][ch][p] = v0 * (1.0f - fr) + v1 * fr;
}

// ---------------- one NCA step: 2 vertical px/thread, full 32 channels, LDC weights ----------------
// Block = 256 threads over a 16x32 pixel tile. tx = tid%16, q = tid/16 (0..15),
// pixels (rl, tx) and (rl+1, tx), rl = 2q. Every weight LDC.128 feeds BOTH pixels.
// Reg cap 128 via __launch_bounds__(256, 2): 32 u64 accs + ~30 temps fits.
__global__ __launch_bounds__(256, 2) void step_kernel(int src, int iter)
{
    __shared__ float tile[C_IN][TH + 2][TW + 4];   // 8 x 34 x 20 floats = 21.8 KB

    int tid = threadIdx.x;
    int col0 = blockIdx.x * TW;
    int row0 = blockIdx.y * TH;

    // load 34x18 halo tile per channel (zero-pad outside)
    for (int i = tid; i < C_IN * 34 * 18; i += 256) {
        int ch = i / (34 * 18);
        int rem = i % (34 * 18);
        int r  = rem / 18;
        int c  = rem % 18;
        int gr = row0 + r - 1, gc = col0 + c - 1;
        float v = 0.0f;
        if ((unsigned)gr < HH && (unsigned)gc < WW)
            v = g_x[src][ch][gr * WW + gc];
        tile[ch][r][c] = v;
    }
    __syncthreads();

    int tx = tid % TW;
    int q  = tid / TW;            // 0..15
    int rl = 2 * q;

    // ---- conv3x3: 2 pixels x 16 packed accumulators (32 channels) ----
    u64 accA[16], accB[16];
    {
        const ulonglong2* bp = (const ulonglong2*)&c_pack[B1P];
        #pragma unroll
        for (int k = 0; k < 8; k++) {
            ulonglong2 v = bp[k];
            accA[2*k] = v.x; accA[2*k+1] = v.y;
            accB[2*k] = v.x; accB[2*k+1] = v.y;
        }
    }

    #pragma unroll 1
    for (int ci = 0; ci < C_IN; ci++) {
        #pragma unroll
        for (int kx = 0; kx < 3; kx++) {
            // one column of 4 x-values feeds 3 taps x 2 pixels
            float xc0 = tile[ci][rl + 0][tx + kx];
            float xc1 = tile[ci][rl + 1][tx + kx];
            float xc2 = tile[ci][rl + 2][tx + kx];
            float xc3 = tile[ci][rl + 3][tx + kx];
            #pragma unroll
            for (int ky = 0; ky < 3; ky++) {
                float xa = (ky == 0) ? xc0 : (ky == 1) ? xc1 : xc2;
                float xb = (ky == 0) ? xc1 : (ky == 1) ? xc2 : xc3;
                u64 x0 = dup2(xa);
                u64 x1 = dup2(xb);
                const ulonglong2* wp =
                    (const ulonglong2*)&c_pack[W1P + (ci * 9 + ky * 3 + kx) * 32];
                #pragma unroll
                for (int j = 0; j < 8; j++) {
                    ulonglong2 w = wp[j];            // LDC.128: 4 weights -> 2 pixels
                    accA[2*j]   = fma2(x0, w.x, accA[2*j]);
                    accA[2*j+1] = fma2(x0, w.y, accA[2*j+1]);
                    accB[2*j]   = fma2(x1, w.x, accB[2*j]);
                    accB[2*j+1] = fma2(x1, w.y, accB[2*j+1]);
                }
            }
        }
    }

    // ---- gelu (exact erf) + conv1x1; W2 loads shared across both pixels ----
    u64 dxA[4], dxB[4];
    {
        const ulonglong2* bp = (const ulonglong2*)&c_pack[B2P];
        ulonglong2 v0 = bp[0], v1 = bp[1];
        dxA[0] = v0.x; dxA[1] = v0.y; dxA[2] = v1.x; dxA[3] = v1.y;
        dxB[0] = v0.x; dxB[1] = v0.y; dxB[2] = v1.x; dxB[3] = v1.y;
    }
    #pragma unroll
    for (int j = 0; j < 16; j++) {
        float a0, a1, b0, b1;
        unpack2(accA[j], a0, a1);
        unpack2(accB[j], b0, b1);
        float ga0 = gelu1(a0), ga1 = gelu1(a1);
        float gb0 = gelu1(b0), gb1 = gelu1(b1);
        {
            // channel 2j
            const ulonglong2* wp = (const ulonglong2*)&c_pack[W2P + (2*j) * 8];
            ulonglong2 wa = wp[0], wb = wp[1];
            u64 gA = dup2(ga0), gB = dup2(gb0);
            dxA[0] = fma2(gA, wa.x, dxA[0]); dxA[1] = fma2(gA, wa.y, dxA[1]);
            dxA[2] = fma2(gA, wb.x, dxA[2]); dxA[3] = fma2(gA, wb.y, dxA[3]);
            dxB[0] = fma2(gB, wa.x, dxB[0]); dxB[1] = fma2(gB, wa.y, dxB[1]);
            dxB[2] = fma2(gB, wb.x, dxB[2]); dxB[3] = fma2(gB, wb.y, dxB[3]);
        }
        {
            // channel 2j+1
            const ulonglong2* wp = (const ulonglong2*)&c_pack[W2P + (2*j+1) * 8];
            ulonglong2 wa = wp[0], wb = wp[1];
            u64 gA = dup2(ga1), gB = dup2(gb1);
            dxA[0] = fma2(gA, wa.x, dxA[0]); dxA[1] = fma2(gA, wa.y, dxA[1]);
            dxA[2] = fma2(gA, wb.x, dxA[2]); dxA[3] = fma2(gA, wb.y, dxA[3]);
            dxB[0] = fma2(gB, wa.x, dxB[0]); dxB[1] = fma2(gB, wa.y, dxB[1]);
            dxB[2] = fma2(gB, wb.x, dxB[2]); dxB[3] = fma2(gB, wb.y, dxB[3]);
        }
    }

    // ---- masked update for both pixels ----
    int col = col0 + tx;
    int dst = src ^ 1;
    #pragma unroll
    for (int s = 0; s < 2; s++) {
        int row = row0 + rl + s;
        int p = row * WW + col;
        unsigned bits = g_mask[iter][p >> 5];
        float m = ((bits >> (p & 31)) & 1u) ? 0.1f : 0.0f;   // fold 0.1 into the mask
        const u64* dx = s ? dxB : dxA;
        #pragma unroll
        for (int k = 0; k < 4; k++) {
            float d0, d1;
            unpack2(dx[k], d0, d1);
            g_x[dst][2*k][p]   = tile[2*k][rl + 1 + s][tx + 1]   + d0 * m;
            g_x[dst][2*k+1][p] = tile[2*k+1][rl + 1 + s][tx + 1] + d1 * m;
        }
    }
}

// ---------------- projection ----------------
__global__ void project_kernel(const float* __restrict__ Wp, const float* __restrict__ bp,
                               float* __restrict__ out) {
    int p = blockIdx.x * blockDim.x + threadIdx.x;
    if (p >= NPIX) return;
    float s = bp[0];
    #pragma unroll
    for (int ch = 0; ch < C_IN; ch++) s += g_x[0][ch][p] * Wp[ch];
    out[p] = s;
}

extern "C" void kernel_launch(void* const* d_in, const int* in_sizes, int n_in,
                              void* d_out, int out_size) {
    const float* seed = (const float*)d_in[0];
    const float* W1   = (const float*)d_in[1];
    const float* b1   = (const float*)d_in[2];
    const float* W2   = (const float*)d_in[3];
    const float* b2   = (const float*)d_in[4];
    const float* Wp   = (const float*)d_in[5];
    const float* bp   = (const float*)d_in[6];
    float* out = (float*)d_out;

    repack_kernel<<<(2600 + 255) / 256, 256>>>(W1, b1, W2, b2);
    // D2D copy of the repacked weights into constant memory (graph-capturable memcpy node)
    {
        const void* src_dev;
        cudaGetSymbolAddress((void**)&src_dev, g_pack);
        cudaMemcpyToSymbolAsync(c_pack, src_dev, sizeof(float) * (2304 + 256 + 32 + 8),
                                0, cudaMemcpyDeviceToDevice, 0);
    }

    upsample_kernel<<<(C_IN * NPIX + 255) / 256, 256>>>(seed);
    genmask_kernel<<<(NIT * 32768) / 256, 256>>>();

    dim3 grid(WW / TW, HH / TH);
    for (int s = 0; s < NIT; s++)
        step_kernel<<<grid, 256>>>(s & 1, s);
    // after 64 steps the result is back in buffer 0
    project_kernel<<<(NPIX + 255) / 256, 256>>>(Wp, bp, out);
}

// round 14
// speedup vs baseline: 1.9623x; 1.1157x over previous
#include <cuda_runtime.h>
#include <cstdint>

#define HH 1024
#define WW 1024
#define NPIX (HH*WW)
#define C_IN 8
#define C_HID 32
#define NIT 64
#define TW 16
#define TH 32

typedef unsigned long long u64;

// Ping-pong state (64 MB) + masks (8 MB) + weight repack staging, static device scratch.
__device__ float g_x[2][C_IN][NPIX];
__device__ unsigned g_mask[NIT][NPIX/32];
__device__ float g_pack[2304 + 256 + 32 + 8];

// Packed weights in constant memory: [tap][o] w1, [hid][o] w2, b1, b2.
#define W1P 0
#define W2P 2304
#define B1P 2560
#define B2P 2592
__constant__ __align__(16) float c_pack[2304 + 256 + 32 + 8];

// ---------------- packed f32x2 helpers ----------------
__device__ __forceinline__ u64 fma2(u64 a, u64 b, u64 c) {
    u64 d;
    asm("fma.rn.f32x2 %0, %1, %2, %3;" : "=l"(d) : "l"(a), "l"(b), "l"(c));
    return d;
}
__device__ __forceinline__ u64 dup2(float x) {
    u64 r;
    asm("mov.b64 %0, {%1, %1};" : "=l"(r) : "f"(x));
    return r;
}
__device__ __forceinline__ void unpack2(u64 v, float& lo, float& hi) {
    asm("mov.b64 {%0, %1}, %2;" : "=f"(lo), "=f"(hi) : "l"(v));
}
__device__ __forceinline__ float gelu1(float h) {
    return 0.5f * h * (1.0f + erff(h * 0.7071067811865476f));
}

// ---------------- threefry2x32 (exact JAX semantics) ----------------
__device__ __forceinline__ uint32_t rotl32(uint32_t x, int d) {
    return (x << d) | (x >> (32 - d));
}
__device__ __forceinline__ void tf_round(uint32_t& x0, uint32_t& x1, int r) {
    x0 += x1; x1 = rotl32(x1, r); x1 ^= x0;
}
__device__ __forceinline__ uint2 threefry(uint32_t k0, uint32_t k1, uint32_t x0, uint32_t x1) {
    uint32_t k2 = k0 ^ k1 ^ 0x1BD11BDAu;
    x0 += k0; x1 += k1;
    tf_round(x0,x1,13); tf_round(x0,x1,15); tf_round(x0,x1,26); tf_round(x0,x1,6);
    x0 += k1; x1 += k2 + 1u;
    tf_round(x0,x1,17); tf_round(x0,x1,29); tf_round(x0,x1,16); tf_round(x0,x1,24);
    x0 += k2; x1 += k0 + 2u;
    tf_round(x0,x1,13); tf_round(x0,x1,15); tf_round(x0,x1,26); tf_round(x0,x1,6);
    x0 += k0; x1 += k1 + 3u;
    tf_round(x0,x1,17); tf_round(x0,x1,29); tf_round(x0,x1,16); tf_round(x0,x1,24);
    x0 += k1; x1 += k2 + 4u;
    tf_round(x0,x1,13); tf_round(x0,x1,15); tf_round(x0,x1,26); tf_round(x0,x1,6);
    x0 += k2; x1 += k0 + 5u;
    return make_uint2(x0, x1);
}

// ---------------- weight repack: OIHW -> [tap][o] (then D2D-copied into c_pack) ----------------
__global__ void repack_kernel(const float* __restrict__ W1, const float* __restrict__ b1,
                              const float* __restrict__ W2, const float* __restrict__ b2) {
    int i = blockIdx.x * blockDim.x + threadIdx.x;   // 2600 items
    if (i < 2304) {
        int o = i / 72, t = i % 72;
        g_pack[W1P + t * 32 + o] = W1[i];
    } else if (i < 2304 + 256) {
        int j = i - 2304;                            // W2: [o][c] -> [c][o]
        int o = j / 32, c = j % 32;
        g_pack[W2P + c * 8 + o] = W2[j];
    } else if (i < 2304 + 256 + 32) {
        g_pack[B1P + (i - 2560)] = b1[i - 2560];
    } else if (i < 2304 + 256 + 32 + 8) {
        g_pack[B2P + (i - 2592)] = b2[i - 2592];
    }
}

// ---------------- mask precompute (jax_threefry_partitionable=True) ----------------
__global__ void genmask_kernel() {
    int gid = blockIdx.x * blockDim.x + threadIdx.x;   // NIT * 32768 threads; 32 pixels each
    int t  = gid >> 15;
    int wq = gid & 32767;
    uint2 kt = threefry(0u, 42u, 0u, (uint32_t)t);
    unsigned m = 0u;
    unsigned base = (unsigned)wq * 32u;
    #pragma unroll 4
    for (int k = 0; k < 32; k++) {
        uint2 rv = threefry(kt.x, kt.y, 0u, base + (unsigned)k);
        uint32_t bits = rv.x ^ rv.y;
        if ((bits >> 9) > 0x400000u) m |= (1u << k);
    }
    g_mask[t][wq] = m;
}

// ---------------- bilinear upsample 8x8 -> 1024x1024 ----------------
__global__ void upsample_kernel(const float* __restrict__ seed) {
    int i = blockIdx.x * blockDim.x + threadIdx.x;
    if (i >= C_IN * NPIX) return;
    int ch = i / NPIX;
    int p  = i % NPIX;
    int r = p / WW, c = p % WW;
    float sr = (r + 0.5f) * (8.0f / HH) - 0.5f;
    float sc = (c + 0.5f) * (8.0f / WW) - 0.5f;
    float fr0 = floorf(sr), fc0 = floorf(sc);
    float fr = sr - fr0,    fc = sc - fc0;
    int r0 = (int)fr0, c0 = (int)fc0;
    int r1 = min(r0 + 1, 7), c1 = min(c0 + 1, 7);
    r0 = max(r0, 0); c0 = max(c0, 0);
    const float* s = seed + ch * 64;
    float v00 = s[r0*8 + c0], v01 = s[r0*8 + c1];
    float v10 = s[r1*8 + c0], v11 = s[r1*8 + c1];
    float v0 = v00 * (1.0f - fc) + v01 * fc;
    float v1 = v10 * (1.0f - fc) + v11 * fc;
    g_x[0][ch][p] = v0 * (1.0f - fr) + v1 * fr;
}

// ---------------- one NCA step: 2 vertical px/thread, channels in 2 sequential passes ----------------
// Block = 256 threads over a 16x32 pixel tile. tx = tid%16, q = tid/16 (0..15),
// pixels (rl, tx) and (rl+1, tx), rl = 2q. Every weight LDC.128 feeds BOTH pixels.
// Hidden channels computed in two passes of 16 to keep live regs ~80 -> 3 CTAs/SM.
__global__ __launch_bounds__(256, 3) void step_kernel(int src, int iter)
{
    __shared__ float tile[C_IN][TH + 2][TW + 4];   // 8 x 34 x 20 floats = 21.8 KB

    int tid = threadIdx.x;
    int col0 = blockIdx.x * TW;
    int row0 = blockIdx.y * TH;

    // load 34x18 halo tile per channel (zero-pad outside)
    for (int i = tid; i < C_IN * 34 * 18; i += 256) {
        int ch = i / (34 * 18);
        int rem = i % (34 * 18);
        int r  = rem / 18;
        int c  = rem % 18;
        int gr = row0 + r - 1, gc = col0 + c - 1;
        float v = 0.0f;
        if ((unsigned)gr < HH && (unsigned)gc < WW)
            v = g_x[src][ch][gr * WW + gc];
        tile[ch][r][c] = v;
    }
    __syncthreads();

    int tx = tid % TW;
    int q  = tid / TW;            // 0..15
    int rl = 2 * q;

    // dx accumulators for both pixels (bias-initialized), built up across both passes
    u64 dxA[4], dxB[4];
    {
        const ulonglong2* bp = (const ulonglong2*)&c_pack[B2P];
        ulonglong2 v0 = bp[0], v1 = bp[1];
        dxA[0] = v0.x; dxA[1] = v0.y; dxA[2] = v1.x; dxA[3] = v1.y;
        dxB[0] = v0.x; dxB[1] = v0.y; dxB[2] = v1.x; dxB[3] = v1.y;
    }

    #pragma unroll 1
    for (int half = 0; half < 2; half++) {
        // ---- conv3x3 for 16 channels of this half, both pixels ----
        u64 accA[8], accB[8];
        {
            const ulonglong2* bp = (const ulonglong2*)&c_pack[B1P + half * 16];
            #pragma unroll
            for (int k = 0; k < 4; k++) {
                ulonglong2 v = bp[k];
                accA[2*k] = v.x; accA[2*k+1] = v.y;
                accB[2*k] = v.x; accB[2*k+1] = v.y;
            }
        }

        #pragma unroll 1
        for (int ci = 0; ci < C_IN; ci++) {
            #pragma unroll
            for (int ky = 0; ky < 3; ky++) {
                #pragma unroll
                for (int kx = 0; kx < 3; kx++) {
                    u64 x0 = dup2(tile[ci][rl + ky][tx + kx]);
                    u64 x1 = dup2(tile[ci][rl + ky + 1][tx + kx]);
                    const ulonglong2* wp =
                        (const ulonglong2*)&c_pack[W1P + (ci * 9 + ky * 3 + kx) * 32 + half * 16];
                    #pragma unroll
                    for (int j = 0; j < 4; j++) {
                        ulonglong2 w = wp[j];        // LDC.128: 4 weights -> 2 pixels
                        accA[2*j]   = fma2(x0, w.x, accA[2*j]);
                        accA[2*j+1] = fma2(x0, w.y, accA[2*j+1]);
                        accB[2*j]   = fma2(x1, w.x, accB[2*j]);
                        accB[2*j+1] = fma2(x1, w.y, accB[2*j+1]);
                    }
                }
            }
        }

        // ---- gelu + partial 1x1 for this half's 16 channels ----
        #pragma unroll
        for (int j = 0; j < 8; j++) {
            float a0, a1, b0, b1;
            unpack2(accA[j], a0, a1);
            unpack2(accB[j], b0, b1);
            float ga0 = gelu1(a0), ga1 = gelu1(a1);
            float gb0 = gelu1(b0), gb1 = gelu1(b1);
            int c0 = half * 16 + 2 * j;
            {
                const ulonglong2* wp = (const ulonglong2*)&c_pack[W2P + c0 * 8];
                ulonglong2 wa = wp[0], wb = wp[1];
                u64 gA = dup2(ga0), gB = dup2(gb0);
                dxA[0] = fma2(gA, wa.x, dxA[0]); dxA[1] = fma2(gA, wa.y, dxA[1]);
                dxA[2] = fma2(gA, wb.x, dxA[2]); dxA[3] = fma2(gA, wb.y, dxA[3]);
                dxB[0] = fma2(gB, wa.x, dxB[0]); dxB[1] = fma2(gB, wa.y, dxB[1]);
                dxB[2] = fma2(gB, wb.x, dxB[2]); dxB[3] = fma2(gB, wb.y, dxB[3]);
            }
            {
                const ulonglong2* wp = (const ulonglong2*)&c_pack[W2P + (c0 + 1) * 8];
                ulonglong2 wa = wp[0], wb = wp[1];
                u64 gA = dup2(ga1), gB = dup2(gb1);
                dxA[0] = fma2(gA, wa.x, dxA[0]); dxA[1] = fma2(gA, wa.y, dxA[1]);
                dxA[2] = fma2(gA, wb.x, dxA[2]); dxA[3] = fma2(gA, wb.y, dxA[3]);
                dxB[0] = fma2(gB, wa.x, dxB[0]); dxB[1] = fma2(gB, wa.y, dxB[1]);
                dxB[2] = fma2(gB, wb.x, dxB[2]); dxB[3] = fma2(gB, wb.y, dxB[3]);
            }
        }
    }

    // ---- masked update for both pixels ----
    int col = col0 + tx;
    int dst = src ^ 1;
    #pragma unroll
    for (int s = 0; s < 2; s++) {
        int row = row0 + rl + s;
        int p = row * WW + col;
        unsigned bits = g_mask[iter][p >> 5];
        float m = ((bits >> (p & 31)) & 1u) ? 0.1f : 0.0f;   // fold 0.1 into the mask
        const u64* dx = s ? dxB : dxA;
        #pragma unroll
        for (int k = 0; k < 4; k++) {
            float d0, d1;
            unpack2(dx[k], d0, d1);
            g_x[dst][2*k][p]   = tile[2*k][rl + 1 + s][tx + 1]   + d0 * m;
            g_x[dst][2*k+1][p] = tile[2*k+1][rl + 1 + s][tx + 1] + d1 * m;
        }
    }
}

// ---------------- projection ----------------
__global__ void project_kernel(const float* __restrict__ Wp, const float* __restrict__ bp,
                               float* __restrict__ out) {
    int p = blockIdx.x * blockDim.x + threadIdx.x;
    if (p >= NPIX) return;
    float s = bp[0];
    #pragma unroll
    for (int ch = 0; ch < C_IN; ch++) s += g_x[0][ch][p] * Wp[ch];
    out[p] = s;
}

extern "C" void kernel_launch(void* const* d_in, const int* in_sizes, int n_in,
                              void* d_out, int out_size) {
    const float* seed = (const float*)d_in[0];
    const float* W1   = (const float*)d_in[1];
    const float* b1   = (const float*)d_in[2];
    const float* W2   = (const float*)d_in[3];
    const float* b2   = (const float*)d_in[4];
    const float* Wp   = (const float*)d_in[5];
    const float* bp   = (const float*)d_in[6];
    float* out = (float*)d_out;

    repack_kernel<<<(2600 + 255) / 256, 256>>>(W1, b1, W2, b2);
    // D2D copy of the repacked weights into constant memory (graph-capturable memcpy node)
    {
        const void* src_dev;
        cudaGetSymbolAddress((void**)&src_dev, g_pack);
        cudaMemcpyToSymbolAsync(c_pack, src_dev, sizeof(float) * (2304 + 256 + 32 + 8),
                                0, cudaMemcpyDeviceToDevice, 0);
    }

    upsample_kernel<<<(C_IN * NPIX + 255) / 256, 256>>>(seed);
    genmask_kernel<<<(NIT * 32768) / 256, 256>>>();

    dim3 grid(WW / TW, HH / TH);
    for (int s = 0; s < NIT; s++)
        step_kernel<<<grid, 256>>>(s & 1, s);
    // after 64 steps the result is back in buffer 0
    project_kernel<<<(NPIX + 255) / 256, 256>>>(Wp, bp, out);
}

// round 15
// speedup vs baseline: 2.0311x; 1.0351x over previous
#include <cuda_runtime.h>
#include <cstdint>

#define HH 1024
#define WW 1024
#define NPIX (HH*WW)
#define C_IN 8
#define C_HID 32
#define NIT 64
#define TW 16
#define TH 32

typedef unsigned long long u64;

// Ping-pong state (64 MB) + masks (8 MB) + weight repack staging, static device scratch.
__device__ float g_x[2][C_IN][NPIX];
__device__ unsigned g_mask[NIT][NPIX/32];
__device__ float g_pack[2304 + 256 + 32 + 8];

// Packed weights in constant memory: [tap][o] w1, [hid][o] w2, b1, b2.
#define W1P 0
#define W2P 2304
#define B1P 2560
#define B2P 2592
__constant__ __align__(16) float c_pack[2304 + 256 + 32 + 8];

// ---------------- packed f32x2 helpers ----------------
__device__ __forceinline__ u64 fma2(u64 a, u64 b, u64 c) {
    u64 d;
    asm("fma.rn.f32x2 %0, %1, %2, %3;" : "=l"(d) : "l"(a), "l"(b), "l"(c));
    return d;
}
__device__ __forceinline__ u64 dup2(float x) {
    u64 r;
    asm("mov.b64 %0, {%1, %1};" : "=l"(r) : "f"(x));
    return r;
}
__device__ __forceinline__ void unpack2(u64 v, float& lo, float& hi) {
    asm("mov.b64 {%0, %1}, %2;" : "=f"(lo), "=f"(hi) : "l"(v));
}
__device__ __forceinline__ float gelu1(float h) {
    return 0.5f * h * (1.0f + erff(h * 0.7071067811865476f));
}

// ---------------- threefry2x32 (exact JAX semantics) ----------------
__device__ __forceinline__ uint32_t rotl32(uint32_t x, int d) {
    return (x << d) | (x >> (32 - d));
}
__device__ __forceinline__ void tf_round(uint32_t& x0, uint32_t& x1, int r) {
    x0 += x1; x1 = rotl32(x1, r); x1 ^= x0;
}
__device__ __forceinline__ uint2 threefry(uint32_t k0, uint32_t k1, uint32_t x0, uint32_t x1) {
    uint32_t k2 = k0 ^ k1 ^ 0x1BD11BDAu;
    x0 += k0; x1 += k1;
    tf_round(x0,x1,13); tf_round(x0,x1,15); tf_round(x0,x1,26); tf_round(x0,x1,6);
    x0 += k1; x1 += k2 + 1u;
    tf_round(x0,x1,17); tf_round(x0,x1,29); tf_round(x0,x1,16); tf_round(x0,x1,24);
    x0 += k2; x1 += k0 + 2u;
    tf_round(x0,x1,13); tf_round(x0,x1,15); tf_round(x0,x1,26); tf_round(x0,x1,6);
    x0 += k0; x1 += k1 + 3u;
    tf_round(x0,x1,17); tf_round(x0,x1,29); tf_round(x0,x1,16); tf_round(x0,x1,24);
    x0 += k1; x1 += k2 + 4u;
    tf_round(x0,x1,13); tf_round(x0,x1,15); tf_round(x0,x1,26); tf_round(x0,x1,6);
    x0 += k2; x1 += k0 + 5u;
    return make_uint2(x0, x1);
}

// ---------------- weight repack: OIHW -> [tap][o] (then D2D-copied into c_pack) ----------------
__global__ void repack_kernel(const float* __restrict__ W1, const float* __restrict__ b1,
                              const float* __restrict__ W2, const float* __restrict__ b2) {
    int i = blockIdx.x * blockDim.x + threadIdx.x;   // 2600 items
    if (i < 2304) {
        int o = i / 72, t = i % 72;
        g_pack[W1P + t * 32 + o] = W1[i];
    } else if (i < 2304 + 256) {
        int j = i - 2304;                            // W2: [o][c] -> [c][o]
        int o = j / 32, c = j % 32;
        g_pack[W2P + c * 8 + o] = W2[j];
    } else if (i < 2304 + 256 + 32) {
        g_pack[B1P + (i - 2560)] = b1[i - 2560];
    } else if (i < 2304 + 256 + 32 + 8) {
        g_pack[B2P + (i - 2592)] = b2[i - 2592];
    }
}

// ---------------- mask precompute (jax_threefry_partitionable=True) ----------------
__global__ void genmask_kernel() {
    int gid = blockIdx.x * blockDim.x + threadIdx.x;   // NIT * 32768 threads; 32 pixels each
    int t  = gid >> 15;
    int wq = gid & 32767;
    uint2 kt = threefry(0u, 42u, 0u, (uint32_t)t);
    unsigned m = 0u;
    unsigned base = (unsigned)wq * 32u;
    #pragma unroll 4
    for (int k = 0; k < 32; k++) {
        uint2 rv = threefry(kt.x, kt.y, 0u, base + (unsigned)k);
        uint32_t bits = rv.x ^ rv.y;
        if ((bits >> 9) > 0x400000u) m |= (1u << k);
    }
    g_mask[t][wq] = m;
}

// ---------------- bilinear upsample 8x8 -> 1024x1024 ----------------
__global__ void upsample_kernel(const float* __restrict__ seed) {
    int i = blockIdx.x * blockDim.x + threadIdx.x;
    if (i >= C_IN * NPIX) return;
    int ch = i / NPIX;
    int p  = i % NPIX;
    int r = p / WW, c = p % WW;
    float sr = (r + 0.5f) * (8.0f / HH) - 0.5f;
    float sc = (c + 0.5f) * (8.0f / WW) - 0.5f;
    float fr0 = floorf(sr), fc0 = floorf(sc);
    float fr = sr - fr0,    fc = sc - fc0;
    int r0 = (int)fr0, c0 = (int)fc0;
    int r1 = min(r0 + 1, 7), c1 = min(c0 + 1, 7);
    r0 = max(r0, 0); c0 = max(c0, 0);
    const float* s = seed + ch * 64;
    float v00 = s[r0*8 + c0], v01 = s[r0*8 + c1];
    float v10 = s[r1*8 + c0], v11 = s[r1*8 + c1];
    float v0 = v00 * (1.0f - fc) + v01 * fc;
    float v1 = v10 * (1.0f - fc) + v11 * fc;
    g_x[0][ch][p] = v0 * (1.0f - fr) + v1 * fr;
}

// ---------------- one NCA step: 2 vertical px/thread, channels in 2 sequential passes ----------------
// Block = 256 threads over a 16x32 pixel tile. tx = tid%16, q = tid/16 (0..15),
// pixels (rl, tx) and (rl+1, tx), rl = 2q. Every weight LDC.128 feeds BOTH pixels.
// Hidden channels computed in two passes of 16; reg cap 64 via (256,4) -> 4 CTAs/SM.
__global__ __launch_bounds__(256, 4) void step_kernel(int src, int iter)
{
    __shared__ float tile[C_IN][TH + 2][TW + 4];   // 8 x 34 x 20 floats = 21.8 KB

    int tid = threadIdx.x;
    int col0 = blockIdx.x * TW;
    int row0 = blockIdx.y * TH;

    // load 34x18 halo tile per channel (zero-pad outside)
    for (int i = tid; i < C_IN * 34 * 18; i += 256) {
        int ch = i / (34 * 18);
        int rem = i % (34 * 18);
        int r  = rem / 18;
        int c  = rem % 18;
        int gr = row0 + r - 1, gc = col0 + c - 1;
        float v = 0.0f;
        if ((unsigned)gr < HH && (unsigned)gc < WW)
            v = g_x[src][ch][gr * WW + gc];
        tile[ch][r][c] = v;
    }
    __syncthreads();

    int tx = tid % TW;
    int q  = tid / TW;            // 0..15
    int rl = 2 * q;

    // dx accumulators for both pixels (bias-initialized), built up across both passes
    u64 dxA[4], dxB[4];
    {
        const ulonglong2* bp = (const ulonglong2*)&c_pack[B2P];
        ulonglong2 v0 = bp[0], v1 = bp[1];
        dxA[0] = v0.x; dxA[1] = v0.y; dxA[2] = v1.x; dxA[3] = v1.y;
        dxB[0] = v0.x; dxB[1] = v0.y; dxB[2] = v1.x; dxB[3] = v1.y;
    }

    #pragma unroll 1
    for (int half = 0; half < 2; half++) {
        // ---- conv3x3 for 16 channels of this half, both pixels ----
        u64 accA[8], accB[8];
        {
            const ulonglong2* bp = (const ulonglong2*)&c_pack[B1P + half * 16];
            #pragma unroll
            for (int k = 0; k < 4; k++) {
                ulonglong2 v = bp[k];
                accA[2*k] = v.x; accA[2*k+1] = v.y;
                accB[2*k] = v.x; accB[2*k+1] = v.y;
            }
        }

        #pragma unroll 1
        for (int ci = 0; ci < C_IN; ci++) {
            #pragma unroll
            for (int ky = 0; ky < 3; ky++) {
                #pragma unroll
                for (int kx = 0; kx < 3; kx++) {
                    u64 x0 = dup2(tile[ci][rl + ky][tx + kx]);
                    u64 x1 = dup2(tile[ci][rl + ky + 1][tx + kx]);
                    const ulonglong2* wp =
                        (const ulonglong2*)&c_pack[W1P + (ci * 9 + ky * 3 + kx) * 32 + half * 16];
                    #pragma unroll
                    for (int j = 0; j < 4; j++) {
                        ulonglong2 w = wp[j];        // LDC.128: 4 weights -> 2 pixels
                        accA[2*j]   = fma2(x0, w.x, accA[2*j]);
                        accA[2*j+1] = fma2(x0, w.y, accA[2*j+1]);
                        accB[2*j]   = fma2(x1, w.x, accB[2*j]);
                        accB[2*j+1] = fma2(x1, w.y, accB[2*j+1]);
                    }
                }
            }
        }

        // ---- gelu + partial 1x1 for this half's 16 channels ----
        #pragma unroll
        for (int j = 0; j < 8; j++) {
            float a0, a1, b0, b1;
            unpack2(accA[j], a0, a1);
            unpack2(accB[j], b0, b1);
            float ga0 = gelu1(a0), ga1 = gelu1(a1);
            float gb0 = gelu1(b0), gb1 = gelu1(b1);
            int c0 = half * 16 + 2 * j;
            {
                const ulonglong2* wp = (const ulonglong2*)&c_pack[W2P + c0 * 8];
                ulonglong2 wa = wp[0], wb = wp[1];
                u64 gA = dup2(ga0), gB = dup2(gb0);
                dxA[0] = fma2(gA, wa.x, dxA[0]); dxA[1] = fma2(gA, wa.y, dxA[1]);
                dxA[2] = fma2(gA, wb.x, dxA[2]); dxA[3] = fma2(gA, wb.y, dxA[3]);
                dxB[0] = fma2(gB, wa.x, dxB[0]); dxB[1] = fma2(gB, wa.y, dxB[1]);
                dxB[2] = fma2(gB, wb.x, dxB[2]); dxB[3] = fma2(gB, wb.y, dxB[3]);
            }
            {
                const ulonglong2* wp = (const ulonglong2*)&c_pack[W2P + (c0 + 1) * 8];
                ulonglong2 wa = wp[0], wb = wp[1];
                u64 gA = dup2(ga1), gB = dup2(gb1);
                dxA[0] = fma2(gA, wa.x, dxA[0]); dxA[1] = fma2(gA, wa.y, dxA[1]);
                dxA[2] = fma2(gA, wb.x, dxA[2]); dxA[3] = fma2(gA, wb.y, dxA[3]);
                dxB[0] = fma2(gB, wa.x, dxB[0]); dxB[1] = fma2(gB, wa.y, dxB[1]);
                dxB[2] = fma2(gB, wb.x, dxB[2]); dxB[3] = fma2(gB, wb.y, dxB[3]);
            }
        }
    }

    // ---- masked update for both pixels ----
    int col = col0 + tx;
    int dst = src ^ 1;
    #pragma unroll
    for (int s = 0; s < 2; s++) {
        int row = row0 + rl + s;
        int p = row * WW + col;
        unsigned bits = g_mask[iter][p >> 5];
        float m = ((bits >> (p & 31)) & 1u) ? 0.1f : 0.0f;   // fold 0.1 into the mask
        const u64* dx = s ? dxB : dxA;
        #pragma unroll
        for (int k = 0; k < 4; k++) {
            float d0, d1;
            unpack2(dx[k], d0, d1);
            g_x[dst][2*k][p]   = tile[2*k][rl + 1 + s][tx + 1]   + d0 * m;
            g_x[dst][2*k+1][p] = tile[2*k+1][rl + 1 + s][tx + 1] + d1 * m;
        }
    }
}

// ---------------- projection ----------------
__global__ void project_kernel(const float* __restrict__ Wp, const float* __restrict__ bp,
                               float* __restrict__ out) {
    int p = blockIdx.x * blockDim.x + threadIdx.x;
    if (p >= NPIX) return;
    float s = bp[0];
    #pragma unroll
    for (int ch = 0; ch < C_IN; ch++) s += g_x[0][ch][p] * Wp[ch];
    out[p] = s;
}

extern "C" void kernel_launch(void* const* d_in, const int* in_sizes, int n_in,
                              void* d_out, int out_size) {
    const float* seed = (const float*)d_in[0];
    const float* W1   = (const float*)d_in[1];
    const float* b1   = (const float*)d_in[2];
    const float* W2   = (const float*)d_in[3];
    const float* b2   = (const float*)d_in[4];
    const float* Wp   = (const float*)d_in[5];
    const float* bp   = (const float*)d_in[6];
    float* out = (float*)d_out;

    repack_kernel<<<(2600 + 255) / 256, 256>>>(W1, b1, W2, b2);
    // D2D copy of the repacked weights into constant memory (graph-capturable memcpy node)
    {
        const void* src_dev;
        cudaGetSymbolAddress((void**)&src_dev, g_pack);
        cudaMemcpyToSymbolAsync(c_pack, src_dev, sizeof(float) * (2304 + 256 + 32 + 8),
                                0, cudaMemcpyDeviceToDevice, 0);
    }

    upsample_kernel<<<(C_IN * NPIX + 255) / 256, 256>>>(seed);
    genmask_kernel<<<(NIT * 32768) / 256, 256>>>();

    dim3 grid(WW / TW, HH / TH);
    for (int s = 0; s < NIT; s++)
        step_kernel<<<grid, 256>>>(s & 1, s);
    // after 64 steps the result is back in buffer 0
    project_kernel<<<(NPIX + 255) / 256, 256>>>(Wp, bp, out);
}